// round 3
// baseline (speedup 1.0000x reference)
#include <cuda_runtime.h>
#include <cuda_bf16.h>
#include <cstdint>

// Problem constants
#define BATCH 32
#define C     192
#define HW    3136            // 56*56
#define CHW   602112          // C*HW
#define T_STEPS 96
#define NSLICE 64             // K-slices for gram GEMM (2 per batch image)
#define KC    1568            // K per slice (HW/2)
#define KT    32              // k-tile
#define STRIDE 68             // padded smem row stride

#define NSLOTS (C + T_STEPS)  // 288 stable slots (slot order == list order)
#define SMEM_D2_BYTES (C * C * 4)   // 147456

// Static device scratch (no allocations allowed)
__device__ float g_partial[NSLICE * 6 * 64 * 64];   // 6 MB
__device__ float g_G[C * C];
__device__ int   g_v1[T_STEPS];
__device__ int   g_v2[T_STEPS];

__constant__ int c_TA[6] = {0, 0, 0, 1, 1, 2};
__constant__ int c_TB[6] = {0, 1, 2, 1, 2, 2};

// ---------------------------------------------------------------------------
// Kernel 1: partial Gram.  Block (ti, s): 64x64 tile ti over K-slice s.
// ---------------------------------------------------------------------------
__global__ __launch_bounds__(256) void gram_kernel(const float* __restrict__ x) {
    __shared__ float As[KT * STRIDE];
    __shared__ float Bs[KT * STRIDE];

    const int ti = blockIdx.x;        // 0..5
    const int s  = blockIdx.y;        // 0..63
    const int rA = c_TA[ti] * 64;
    const int rB = c_TB[ti] * 64;
    const int b   = s >> 1;
    const int hw0 = (s & 1) * KC;
    const float* xb = x + (size_t)b * CHW + hw0;

    const int tid = threadIdx.x;
    const int my  = tid >> 4;         // 0..15
    const int nx  = tid & 15;         // 0..15

    float acc[4][4];
#pragma unroll
    for (int i = 0; i < 4; i++)
#pragma unroll
        for (int j = 0; j < 4; j++) acc[i][j] = 0.0f;

    for (int kk = 0; kk < KC; kk += KT) {
#pragma unroll
        for (int i = 0; i < 2; i++) {
            int e4 = tid + i * 256;
            int m  = e4 >> 3;
            int k4 = e4 & 7;
            const float4 a = *(const float4*)(xb + (size_t)(rA + m) * HW + kk + 4 * k4);
            const float4 c = *(const float4*)(xb + (size_t)(rB + m) * HW + kk + 4 * k4);
            As[(4 * k4 + 0) * STRIDE + m] = a.x;
            As[(4 * k4 + 1) * STRIDE + m] = a.y;
            As[(4 * k4 + 2) * STRIDE + m] = a.z;
            As[(4 * k4 + 3) * STRIDE + m] = a.w;
            Bs[(4 * k4 + 0) * STRIDE + m] = c.x;
            Bs[(4 * k4 + 1) * STRIDE + m] = c.y;
            Bs[(4 * k4 + 2) * STRIDE + m] = c.z;
            Bs[(4 * k4 + 3) * STRIDE + m] = c.w;
        }
        __syncthreads();
#pragma unroll
        for (int k = 0; k < KT; k++) {
            const float4 a4 = *(const float4*)&As[k * STRIDE + 4 * my];
            const float4 b4 = *(const float4*)&Bs[k * STRIDE + 4 * nx];
            const float av[4] = {a4.x, a4.y, a4.z, a4.w};
            const float bv[4] = {b4.x, b4.y, b4.z, b4.w};
#pragma unroll
            for (int i = 0; i < 4; i++)
#pragma unroll
                for (int j = 0; j < 4; j++)
                    acc[i][j] = fmaf(av[i], bv[j], acc[i][j]);
        }
        __syncthreads();
    }

    float* out = g_partial + ((size_t)s * 6 + ti) * 4096;
#pragma unroll
    for (int i = 0; i < 4; i++)
#pragma unroll
        for (int j = 0; j < 4; j++)
            out[(4 * my + i) * 64 + (4 * nx + j)] = acc[i][j];
}

// ---------------------------------------------------------------------------
// Kernel 2: reduce partials over slices -> symmetric G
// ---------------------------------------------------------------------------
__global__ __launch_bounds__(256) void reduce_kernel() {
    const int gid = blockIdx.x * 256 + threadIdx.x;
    if (gid >= 6 * 4096) return;
    const int ti = gid >> 12;
    const int r  = gid & 4095;
    const int m  = r >> 6;
    const int nn = r & 63;
    float ssum = 0.0f;
#pragma unroll 8
    for (int s = 0; s < NSLICE; s++)
        ssum += g_partial[((size_t)s * 6 + ti) * 4096 + r];
    const int gi = c_TA[ti] * 64 + m;
    const int gj = c_TB[ti] * 64 + nn;
    g_G[gi * C + gj] = ssum;
    g_G[gj * C + gi] = ssum;
}

// ---------------------------------------------------------------------------
// Kernel 3: greedy selection with per-row minima over stable slots.
//
// Slot s holds the list entry created s-th (0..191 initial, 192+t appended).
// Slot order == list-position order at all times, so argmin over keys
// (dbits, s, s_partner) reproduces row-major first-occurrence argmin exactly.
// Removal never lowers a surviving row's min, so only rows whose stored
// partner was removed rescan; everyone else does one O(1) update vs the
// appended slot.
// ---------------------------------------------------------------------------
__global__ __launch_bounds__(512) void select_kernel() {
    extern __shared__ float sD2[];                       // C*C floats
    __shared__ int  s_alive[NSLOTS];
    __shared__ int  s_chan[NSLOTS];                      // original-channel id
    __shared__ unsigned long long s_minkey[NSLOTS];      // (dbits<<32)|partner
    __shared__ unsigned long long warpmin[16];
    __shared__ int s_si, s_sj;

    const int tid = threadIdx.x;

    // Build D2 in shared memory from Gram matrix.
    for (int id = tid; id < C * C; id += 512) {
        const int i = id / C;
        const int j = id - i * C;
        float d = 0.0f;
        if (i != j) {
            d = g_G[i * C + i] + g_G[j * C + j] - 2.0f * g_G[i * C + j];
            d = fmaxf(d, 0.0f);
        }
        sD2[id] = d;
    }
    if (tid < NSLOTS) {
        s_alive[tid] = (tid < C) ? 1 : 0;
        s_chan[tid]  = (tid < C) ? tid : 0;
        s_minkey[tid] = ~0ull;
    }
    __syncthreads();

    // Initial row minima for slots 0..190 (slot 191 has empty candidate set).
    if (tid < C - 1) {
        const int row = tid * C;
        unsigned long long best = ~0ull;
        for (int sp = tid + 1; sp < C; sp++) {
            const float d = sD2[row + sp];
            const unsigned long long key =
                ((unsigned long long)__float_as_uint(d) << 32) | (unsigned)sp;
            if (key < best) best = key;
        }
        s_minkey[tid] = best;
    }
    __syncthreads();

    for (int t = 0; t < T_STEPS; t++) {
        const int sn = C + t;   // slot for the element appended this step

        // ---- global argmin over row minima ----
        unsigned long long best = ~0ull;
        if (tid < sn && s_alive[tid]) {
            const unsigned long long mk = s_minkey[tid];
            if (mk != ~0ull) {
                const unsigned long long db = mk >> 32;
                const unsigned long long part = mk & 0x1ffull;
                best = (db << 18) | ((unsigned long long)tid << 9) | part;
            }
        }
#pragma unroll
        for (int o = 16; o > 0; o >>= 1) {
            unsigned long long other = __shfl_down_sync(0xffffffffu, best, o);
            if (other < best) best = other;
        }
        if ((tid & 31) == 0) warpmin[tid >> 5] = best;
        __syncthreads();
        if (tid < 32) {
            best = (tid < 16) ? warpmin[tid] : ~0ull;
#pragma unroll
            for (int o = 8; o > 0; o >>= 1) {
                unsigned long long other = __shfl_down_sync(0xffffffffu, best, o);
                if (other < best) best = other;
            }
            if (tid == 0) {
                const int si = (int)((best >> 9) & 0x1ff);
                const int sj = (int)(best & 0x1ff);
                s_si = si; s_sj = sj;
                g_v1[t] = s_chan[si];
                g_v2[t] = s_chan[sj];
                s_alive[si] = 0;
                s_alive[sj] = 0;
                s_alive[sn] = 1;
                s_chan[sn]  = t;          // the replicated indexing bug
                s_minkey[sn] = ~0ull;     // no higher-slot partners
            }
        }
        __syncthreads();

        // ---- row maintenance ----
        const int si = s_si, sj = s_sj;
        if (tid < sn && s_alive[tid]) {
            const unsigned long long mk = s_minkey[tid];
            const int part = (int)(mk & 0x1ffull);
            const int rowbase = s_chan[tid] * C;
            if (mk != ~0ull && (part == si || part == sj)) {
                // stored partner was removed: rescan candidates (incl. sn)
                unsigned long long b = ~0ull;
                for (int sp = tid + 1; sp <= sn; sp++) {
                    if (s_alive[sp]) {
                        const float d = sD2[rowbase + s_chan[sp]];
                        const unsigned long long key =
                            ((unsigned long long)__float_as_uint(d) << 32) |
                            (unsigned)sp;
                        if (key < b) b = key;
                    }
                }
                s_minkey[tid] = b;
            } else {
                // only new candidate is the appended slot
                const float d = sD2[rowbase + t];
                const unsigned long long key =
                    ((unsigned long long)__float_as_uint(d) << 32) |
                    (unsigned)sn;
                if (key < mk) s_minkey[tid] = key;
            }
        }
        __syncthreads();
    }
}

// ---------------------------------------------------------------------------
// Kernel 4: gather + average -> out[b][t][hw]
// ---------------------------------------------------------------------------
__global__ __launch_bounds__(256) void gather_kernel(const float* __restrict__ x,
                                                     float* __restrict__ out) {
    const int t = blockIdx.x;
    const int b = blockIdx.y;
    const int v1 = g_v1[t];
    const int v2 = g_v2[t];
    const float4* p1 = (const float4*)(x + ((size_t)b * C + v1) * HW);
    const float4* p2 = (const float4*)(x + ((size_t)b * C + v2) * HW);
    float4* po = (float4*)(out + ((size_t)b * T_STEPS + t) * HW);
    for (int q = threadIdx.x; q < HW / 4; q += blockDim.x) {
        const float4 a = p1[q];
        const float4 c = p2[q];
        float4 r;
        r.x = 0.5f * (a.x + c.x);
        r.y = 0.5f * (a.y + c.y);
        r.z = 0.5f * (a.z + c.z);
        r.w = 0.5f * (a.w + c.w);
        po[q] = r;
    }
}

// ---------------------------------------------------------------------------
extern "C" void kernel_launch(void* const* d_in, const int* in_sizes, int n_in,
                              void* d_out, int out_size) {
    const float* x = (const float*)d_in[0];
    float* out = (float*)d_out;

    static bool attr_set = false;
    if (!attr_set) {
        cudaFuncSetAttribute(select_kernel,
                             cudaFuncAttributeMaxDynamicSharedMemorySize,
                             SMEM_D2_BYTES);
        attr_set = true;
    }

    gram_kernel<<<dim3(6, NSLICE), 256>>>(x);
    reduce_kernel<<<96, 256>>>();
    select_kernel<<<1, 512, SMEM_D2_BYTES>>>();
    gather_kernel<<<dim3(T_STEPS, BATCH), 256>>>(x, out);
}

// round 5
// speedup vs baseline: 1.7741x; 1.7741x over previous
#include <cuda_runtime.h>
#include <cuda_bf16.h>
#include <cstdint>

// Problem constants
#define BATCH 32
#define C     192
#define HW    3136            // 56*56
#define CHW   602112          // C*HW
#define T_STEPS 96
#define NSLICE 64             // K-slices (2 per batch image)
#define KC    1568            // K per slice (HW/2)
#define KCHUNK 32             // k per smem chunk
#define NCHUNK (KC / KCHUNK)  // 49
#define SSTR  40              // smem bf16 row stride (32 + 8 pad)

#define SMEM_D2_BYTES (C * C * 4)        // 147456
#define GRAM_SMEM_BYTES ((128 + 128 + 192 + 192) * SSTR * 2)   // 51200

// Static device scratch (no allocations allowed)
__device__ float g_partial[NSLICE * 2 * 128 * 192];   // 12.6 MB
__device__ float g_G[C * C];
__device__ int   g_v1[T_STEPS];
__device__ int   g_v2[T_STEPS];

// ---------------------------------------------------------------------------
// ldmatrix / mma wrappers
// ---------------------------------------------------------------------------
__device__ __forceinline__ uint32_t smem_u32(const void* p) {
    return (uint32_t)__cvta_generic_to_shared(p);
}
__device__ __forceinline__ void ldsm_x4(uint32_t* r, uint32_t addr) {
    asm volatile("ldmatrix.sync.aligned.m8n8.x4.shared.b16 {%0,%1,%2,%3}, [%4];"
                 : "=r"(r[0]), "=r"(r[1]), "=r"(r[2]), "=r"(r[3]) : "r"(addr));
}
__device__ __forceinline__ void ldsm_x2(uint32_t* r, uint32_t addr) {
    asm volatile("ldmatrix.sync.aligned.m8n8.x2.shared.b16 {%0,%1}, [%2];"
                 : "=r"(r[0]), "=r"(r[1]) : "r"(addr));
}
__device__ __forceinline__ void mma16816(float* c, const uint32_t* a, const uint32_t* b) {
    asm volatile(
        "mma.sync.aligned.m16n8k16.row.col.f32.bf16.bf16.f32 "
        "{%0,%1,%2,%3}, {%4,%5,%6,%7}, {%8,%9}, {%0,%1,%2,%3};"
        : "+f"(c[0]), "+f"(c[1]), "+f"(c[2]), "+f"(c[3])
        : "r"(a[0]), "r"(a[1]), "r"(a[2]), "r"(a[3]), "r"(b[0]), "r"(b[1]));
}
__device__ __forceinline__ uint32_t pack_bf2(__nv_bfloat16 lo, __nv_bfloat16 hi) {
    return ((uint32_t)__bfloat16_as_ushort(hi) << 16) | (uint32_t)__bfloat16_as_ushort(lo);
}

// ---------------------------------------------------------------------------
// Kernel 1: partial Gram via bf16 hi/lo mma.sync.
// Block (bm, s): M-block bm over K-slice s. M-block0 = rows 0..127 (owns 0..95),
// M-block1 = rows 64..191 (owns 96..191). N = all 192 columns.
// G ~= hi*hi^T + hi*lo^T + lo*hi^T  (lo*lo^T term ~0.13 abs, uniform; safe).
// ---------------------------------------------------------------------------
__global__ void __launch_bounds__(256, 1) gram_mma_kernel(const float* __restrict__ x) {
    extern __shared__ __align__(16) uint8_t smem_raw[];
    __nv_bfloat16* sAhi = (__nv_bfloat16*)smem_raw;                    // [128][SSTR]
    __nv_bfloat16* sAlo = sAhi + 128 * SSTR;
    __nv_bfloat16* sBhi = sAlo + 128 * SSTR;                           // [192][SSTR]
    __nv_bfloat16* sBlo = sBhi + 192 * SSTR;

    const int bm = blockIdx.x;         // 0,1
    const int s  = blockIdx.y;         // 0..63
    const int m0 = bm * 64;
    const int b   = s >> 1;
    const int hw0 = (s & 1) * KC;
    const float* xs = x + (size_t)b * CHW + hw0;

    const int tid  = threadIdx.x;
    const int wid  = tid >> 5;
    const int lane = tid & 31;
    const int wm = (wid & 1) * 64;     // warp M offset (0 or 64)
    const int wn = (wid >> 1) * 48;    // warp N offset (0,48,96,144)

    float acc[4][6][4];
#pragma unroll
    for (int ms = 0; ms < 4; ms++)
#pragma unroll
        for (int ns = 0; ns < 6; ns++)
#pragma unroll
            for (int e = 0; e < 4; e++) acc[ms][ns][e] = 0.0f;

    // ldmatrix lane addresses (byte offsets vary only by k-step)
    const int aRow = wm + (lane & 15);
    const int aK   = (lane >> 4) * 8;
    const uint32_t aHiBase = smem_u32(sAhi + aRow * SSTR + aK);
    const uint32_t aLoBase = smem_u32(sAlo + aRow * SSTR + aK);
    const int bRowL = lane & 7;
    const int bK    = ((lane >> 3) & 1) * 8;   // lanes 0-7: k0 tile, 8-15: k8 tile
    const uint32_t bHiBase = smem_u32(sBhi + (wn + bRowL) * SSTR + bK);
    const uint32_t bLoBase = smem_u32(sBlo + (wn + bRowL) * SSTR + bK);

    for (int chunk = 0; chunk < NCHUNK; chunk++) {
        const int k0 = chunk * KCHUNK;

        // ---- load fp32, split to hi/lo bf16, store smem ----
#pragma unroll
        for (int it = 0; it < 10; it++) {
            const int idx = tid + it * 256;           // 0..2559
            const bool isA = idx < 1024;
            const int r  = isA ? (idx >> 3) : ((idx - 1024) >> 3);
            const int k4 = (idx & 7) * 4;
            const int grow = isA ? (m0 + r) : r;
            const float4 f = *(const float4*)(xs + (size_t)grow * HW + k0 + k4);
            __nv_bfloat16 h0 = __float2bfloat16(f.x);
            __nv_bfloat16 h1 = __float2bfloat16(f.y);
            __nv_bfloat16 h2 = __float2bfloat16(f.z);
            __nv_bfloat16 h3 = __float2bfloat16(f.w);
            __nv_bfloat16 l0 = __float2bfloat16(f.x - __bfloat162float(h0));
            __nv_bfloat16 l1 = __float2bfloat16(f.y - __bfloat162float(h1));
            __nv_bfloat16 l2 = __float2bfloat16(f.z - __bfloat162float(h2));
            __nv_bfloat16 l3 = __float2bfloat16(f.w - __bfloat162float(h3));
            __nv_bfloat16* dh = (isA ? sAhi : sBhi) + r * SSTR + k4;
            __nv_bfloat16* dl = (isA ? sAlo : sBlo) + r * SSTR + k4;
            *(uint2*)dh = make_uint2(pack_bf2(h0, h1), pack_bf2(h2, h3));
            *(uint2*)dl = make_uint2(pack_bf2(l0, l1), pack_bf2(l2, l3));
        }
        __syncthreads();

        // ---- two k16 steps ----
#pragma unroll
        for (int kk2 = 0; kk2 < 2; kk2++) {
            const uint32_t koff = kk2 * 16 * 2;   // byte offset
            uint32_t ahi[4][4], alo[4][4];
#pragma unroll
            for (int ms = 0; ms < 4; ms++) {
                ldsm_x4(ahi[ms], aHiBase + ms * (16 * SSTR * 2) + koff);
                ldsm_x4(alo[ms], aLoBase + ms * (16 * SSTR * 2) + koff);
            }
            uint32_t bhi[6][2], blo[6][2];
#pragma unroll
            for (int ns = 0; ns < 6; ns++) {
                ldsm_x2(bhi[ns], bHiBase + ns * (8 * SSTR * 2) + koff);
                ldsm_x2(blo[ns], bLoBase + ns * (8 * SSTR * 2) + koff);
            }
#pragma unroll
            for (int ms = 0; ms < 4; ms++)
#pragma unroll
                for (int ns = 0; ns < 6; ns++) {
                    mma16816(acc[ms][ns], ahi[ms], bhi[ns]);
                    mma16816(acc[ms][ns], ahi[ms], blo[ns]);
                    mma16816(acc[ms][ns], alo[ms], bhi[ns]);
                }
        }
        __syncthreads();
    }

    // ---- epilogue: write partials ----
    float* outp = g_partial + ((size_t)s * 2 + bm) * (128 * 192);
    const int lr = lane >> 2;
    const int lc = (lane & 3) * 2;
#pragma unroll
    for (int ms = 0; ms < 4; ms++)
#pragma unroll
        for (int ns = 0; ns < 6; ns++) {
            const int row = wm + ms * 16 + lr;
            const int col = wn + ns * 8 + lc;
            *(float2*)(outp + row * 192 + col) =
                make_float2(acc[ms][ns][0], acc[ms][ns][1]);
            *(float2*)(outp + (row + 8) * 192 + col) =
                make_float2(acc[ms][ns][2], acc[ms][ns][3]);
        }
}

// ---------------------------------------------------------------------------
// Kernel 2: reduce partials over slices -> G (disjoint row ownership)
// ---------------------------------------------------------------------------
__global__ __launch_bounds__(256) void reduce_kernel() {
    const int gid = blockIdx.x * 256 + threadIdx.x;
    if (gid >= C * C) return;
    const int r = gid / C;
    const int j = gid - r * C;
    const int bm = (r >= 96) ? 1 : 0;
    const int lr = r - bm * 64;
    float ssum = 0.0f;
#pragma unroll 8
    for (int s = 0; s < NSLICE; s++)
        ssum += g_partial[((size_t)s * 2 + bm) * (128 * 192) + lr * 192 + j];
    g_G[r * C + j] = ssum;
}

// ---------------------------------------------------------------------------
// Kernel 3: greedy selection — warp-per-row triangular scan.
// ---------------------------------------------------------------------------
__global__ __launch_bounds__(1024) void select_kernel() {
    extern __shared__ float sD2[];              // C*C floats
    __shared__ int sidx[2][C];
    __shared__ unsigned long long warpmin[32];
    __shared__ int s_ij;

    const int tid  = threadIdx.x;
    const int wid  = tid >> 5;
    const int lane = tid & 31;

    // Build D2 in shared memory from Gram matrix.
    for (int id = tid; id < C * C; id += 1024) {
        const int i = id / C;
        const int j = id - i * C;
        float d = 0.0f;
        if (i != j) {
            d = g_G[i * C + i] + g_G[j * C + j] - 2.0f * g_G[i * C + j];
            d = fmaxf(d, 0.0f);
        }
        sD2[id] = d;
    }
    if (tid < C) sidx[0][tid] = tid;
    __syncthreads();

    for (int t = 0; t < T_STEPS; t++) {
        const int cur = t & 1, nxt = cur ^ 1;
        const int n = C - t;

        float bestd = 3.4e38f;
        int bestij = 0x7fffffff;
        for (int i = wid; i < n - 1; i += 32) {
            const int rowbase = sidx[cur][i] * C;   // broadcast LDS
            for (int j = i + 1 + lane; j < n; j += 32) {
                const float d = sD2[rowbase + sidx[cur][j]];
                if (d < bestd) { bestd = d; bestij = i * C + j; }
            }
        }
        unsigned long long best =
            ((unsigned long long)__float_as_uint(bestd) << 32) | (unsigned)bestij;
#pragma unroll
        for (int o = 16; o > 0; o >>= 1) {
            unsigned long long other = __shfl_down_sync(0xffffffffu, best, o);
            if (other < best) best = other;
        }
        if (lane == 0) warpmin[wid] = best;
        __syncthreads();
        if (tid < 32) {
            best = warpmin[tid];
#pragma unroll
            for (int o = 16; o > 0; o >>= 1) {
                unsigned long long other = __shfl_down_sync(0xffffffffu, best, o);
                if (other < best) best = other;
            }
            if (tid == 0) {
                const int ij = (int)(best & 0xffffffffull);
                s_ij = ij;
                const int i = ij / C;
                const int j = ij - i * C;
                g_v1[t] = sidx[cur][i];
                g_v2[t] = sidx[cur][j];
            }
        }
        __syncthreads();
        const int ij = s_ij;
        const int i = ij / C;
        const int j = ij - i * C;
        if (tid < n && tid != i && tid != j) {
            const int dest = tid - (tid > i) - (tid > j);
            sidx[nxt][dest] = sidx[cur][tid];
        }
        if (tid == 0) sidx[nxt][n - 2] = t;
        __syncthreads();
    }
}

// ---------------------------------------------------------------------------
// Kernel 4: gather + average -> out[b][t][hw]
// ---------------------------------------------------------------------------
__global__ __launch_bounds__(256) void gather_kernel(const float* __restrict__ x,
                                                     float* __restrict__ out) {
    const int t = blockIdx.x;
    const int b = blockIdx.y;
    const int v1 = g_v1[t];
    const int v2 = g_v2[t];
    const float4* p1 = (const float4*)(x + ((size_t)b * C + v1) * HW);
    const float4* p2 = (const float4*)(x + ((size_t)b * C + v2) * HW);
    float4* po = (float4*)(out + ((size_t)b * T_STEPS + t) * HW);
    for (int q = threadIdx.x; q < HW / 4; q += blockDim.x) {
        const float4 a = p1[q];
        const float4 c = p2[q];
        float4 r;
        r.x = 0.5f * (a.x + c.x);
        r.y = 0.5f * (a.y + c.y);
        r.z = 0.5f * (a.z + c.z);
        r.w = 0.5f * (a.w + c.w);
        po[q] = r;
    }
}

// ---------------------------------------------------------------------------
extern "C" void kernel_launch(void* const* d_in, const int* in_sizes, int n_in,
                              void* d_out, int out_size) {
    const float* x = (const float*)d_in[0];
    float* out = (float*)d_out;

    static bool attr_set = false;
    if (!attr_set) {
        cudaFuncSetAttribute(select_kernel,
                             cudaFuncAttributeMaxDynamicSharedMemorySize,
                             SMEM_D2_BYTES);
        cudaFuncSetAttribute(gram_mma_kernel,
                             cudaFuncAttributeMaxDynamicSharedMemorySize,
                             GRAM_SMEM_BYTES);
        attr_set = true;
    }

    gram_mma_kernel<<<dim3(2, NSLICE), 256, GRAM_SMEM_BYTES>>>(x);
    reduce_kernel<<<144, 256>>>();
    select_kernel<<<1, 1024, SMEM_D2_BYTES>>>();
    gather_kernel<<<dim3(T_STEPS, BATCH), 256>>>(x, out);
}

// round 6
// speedup vs baseline: 2.0025x; 1.1287x over previous
#include <cuda_runtime.h>
#include <cuda_bf16.h>
#include <cstdint>

// Problem constants
#define BATCH 32
#define C     192
#define HW    3136            // 56*56
#define CHW   602112          // C*HW
#define T_STEPS 96
#define NSLICE 64             // K-slices (2 per batch image)
#define KC    1568            // K per slice (HW/2)
#define KCHUNK 32             // k per smem chunk
#define NCHUNK (KC / KCHUNK)  // 49
#define SSTR  40              // smem bf16 row stride (32 + 8 pad)

#define NSLOTS (C + T_STEPS)  // 288
#define SMEM_D2_BYTES (C * C * 4)        // 147456
#define GRAM_SMEM_BYTES ((128 + 128 + 192 + 192) * SSTR * 2)   // 51200

// Static device scratch (no allocations allowed)
__device__ float g_partial[NSLICE * 2 * 128 * 192];   // 12.6 MB
__device__ float g_G[C * C];
__device__ int   g_v1[T_STEPS];
__device__ int   g_v2[T_STEPS];

// ---------------------------------------------------------------------------
// ldmatrix / mma wrappers
// ---------------------------------------------------------------------------
__device__ __forceinline__ uint32_t smem_u32(const void* p) {
    return (uint32_t)__cvta_generic_to_shared(p);
}
__device__ __forceinline__ void ldsm_x4(uint32_t* r, uint32_t addr) {
    asm volatile("ldmatrix.sync.aligned.m8n8.x4.shared.b16 {%0,%1,%2,%3}, [%4];"
                 : "=r"(r[0]), "=r"(r[1]), "=r"(r[2]), "=r"(r[3]) : "r"(addr));
}
__device__ __forceinline__ void ldsm_x2(uint32_t* r, uint32_t addr) {
    asm volatile("ldmatrix.sync.aligned.m8n8.x2.shared.b16 {%0,%1}, [%2];"
                 : "=r"(r[0]), "=r"(r[1]) : "r"(addr));
}
__device__ __forceinline__ void mma16816(float* c, const uint32_t* a, const uint32_t* b) {
    asm volatile(
        "mma.sync.aligned.m16n8k16.row.col.f32.bf16.bf16.f32 "
        "{%0,%1,%2,%3}, {%4,%5,%6,%7}, {%8,%9}, {%0,%1,%2,%3};"
        : "+f"(c[0]), "+f"(c[1]), "+f"(c[2]), "+f"(c[3])
        : "r"(a[0]), "r"(a[1]), "r"(a[2]), "r"(a[3]), "r"(b[0]), "r"(b[1]));
}
__device__ __forceinline__ uint32_t pack_bf2(__nv_bfloat16 lo, __nv_bfloat16 hi) {
    return ((uint32_t)__bfloat16_as_ushort(hi) << 16) | (uint32_t)__bfloat16_as_ushort(lo);
}

// ---------------------------------------------------------------------------
// Kernel 1: partial Gram via bf16 hi/lo mma.sync. (unchanged from R5)
// ---------------------------------------------------------------------------
__global__ void __launch_bounds__(256, 1) gram_mma_kernel(const float* __restrict__ x) {
    extern __shared__ __align__(16) uint8_t smem_raw[];
    __nv_bfloat16* sAhi = (__nv_bfloat16*)smem_raw;                    // [128][SSTR]
    __nv_bfloat16* sAlo = sAhi + 128 * SSTR;
    __nv_bfloat16* sBhi = sAlo + 128 * SSTR;                           // [192][SSTR]
    __nv_bfloat16* sBlo = sBhi + 192 * SSTR;

    const int bm = blockIdx.x;         // 0,1
    const int s  = blockIdx.y;         // 0..63
    const int m0 = bm * 64;
    const int b   = s >> 1;
    const int hw0 = (s & 1) * KC;
    const float* xs = x + (size_t)b * CHW + hw0;

    const int tid  = threadIdx.x;
    const int wid  = tid >> 5;
    const int lane = tid & 31;
    const int wm = (wid & 1) * 64;
    const int wn = (wid >> 1) * 48;

    float acc[4][6][4];
#pragma unroll
    for (int ms = 0; ms < 4; ms++)
#pragma unroll
        for (int ns = 0; ns < 6; ns++)
#pragma unroll
            for (int e = 0; e < 4; e++) acc[ms][ns][e] = 0.0f;

    const int aRow = wm + (lane & 15);
    const int aK   = (lane >> 4) * 8;
    const uint32_t aHiBase = smem_u32(sAhi + aRow * SSTR + aK);
    const uint32_t aLoBase = smem_u32(sAlo + aRow * SSTR + aK);
    const int bRowL = lane & 7;
    const int bK    = ((lane >> 3) & 1) * 8;
    const uint32_t bHiBase = smem_u32(sBhi + (wn + bRowL) * SSTR + bK);
    const uint32_t bLoBase = smem_u32(sBlo + (wn + bRowL) * SSTR + bK);

    for (int chunk = 0; chunk < NCHUNK; chunk++) {
        const int k0 = chunk * KCHUNK;
#pragma unroll
        for (int it = 0; it < 10; it++) {
            const int idx = tid + it * 256;
            const bool isA = idx < 1024;
            const int r  = isA ? (idx >> 3) : ((idx - 1024) >> 3);
            const int k4 = (idx & 7) * 4;
            const int grow = isA ? (m0 + r) : r;
            const float4 f = *(const float4*)(xs + (size_t)grow * HW + k0 + k4);
            __nv_bfloat16 h0 = __float2bfloat16(f.x);
            __nv_bfloat16 h1 = __float2bfloat16(f.y);
            __nv_bfloat16 h2 = __float2bfloat16(f.z);
            __nv_bfloat16 h3 = __float2bfloat16(f.w);
            __nv_bfloat16 l0 = __float2bfloat16(f.x - __bfloat162float(h0));
            __nv_bfloat16 l1 = __float2bfloat16(f.y - __bfloat162float(h1));
            __nv_bfloat16 l2 = __float2bfloat16(f.z - __bfloat162float(h2));
            __nv_bfloat16 l3 = __float2bfloat16(f.w - __bfloat162float(h3));
            __nv_bfloat16* dh = (isA ? sAhi : sBhi) + r * SSTR + k4;
            __nv_bfloat16* dl = (isA ? sAlo : sBlo) + r * SSTR + k4;
            *(uint2*)dh = make_uint2(pack_bf2(h0, h1), pack_bf2(h2, h3));
            *(uint2*)dl = make_uint2(pack_bf2(l0, l1), pack_bf2(l2, l3));
        }
        __syncthreads();
#pragma unroll
        for (int kk2 = 0; kk2 < 2; kk2++) {
            const uint32_t koff = kk2 * 16 * 2;
            uint32_t ahi[4][4], alo[4][4];
#pragma unroll
            for (int ms = 0; ms < 4; ms++) {
                ldsm_x4(ahi[ms], aHiBase + ms * (16 * SSTR * 2) + koff);
                ldsm_x4(alo[ms], aLoBase + ms * (16 * SSTR * 2) + koff);
            }
            uint32_t bhi[6][2], blo[6][2];
#pragma unroll
            for (int ns = 0; ns < 6; ns++) {
                ldsm_x2(bhi[ns], bHiBase + ns * (8 * SSTR * 2) + koff);
                ldsm_x2(blo[ns], bLoBase + ns * (8 * SSTR * 2) + koff);
            }
#pragma unroll
            for (int ms = 0; ms < 4; ms++)
#pragma unroll
                for (int ns = 0; ns < 6; ns++) {
                    mma16816(acc[ms][ns], ahi[ms], bhi[ns]);
                    mma16816(acc[ms][ns], ahi[ms], blo[ns]);
                    mma16816(acc[ms][ns], alo[ms], bhi[ns]);
                }
        }
        __syncthreads();
    }

    float* outp = g_partial + ((size_t)s * 2 + bm) * (128 * 192);
    const int lr = lane >> 2;
    const int lc = (lane & 3) * 2;
#pragma unroll
    for (int ms = 0; ms < 4; ms++)
#pragma unroll
        for (int ns = 0; ns < 6; ns++) {
            const int row = wm + ms * 16 + lr;
            const int col = wn + ns * 8 + lc;
            *(float2*)(outp + row * 192 + col) =
                make_float2(acc[ms][ns][0], acc[ms][ns][1]);
            *(float2*)(outp + (row + 8) * 192 + col) =
                make_float2(acc[ms][ns][2], acc[ms][ns][3]);
        }
}

// ---------------------------------------------------------------------------
// Kernel 2: reduce partials over slices -> G (unchanged)
// ---------------------------------------------------------------------------
__global__ __launch_bounds__(256) void reduce_kernel() {
    const int gid = blockIdx.x * 256 + threadIdx.x;
    if (gid >= C * C) return;
    const int r = gid / C;
    const int j = gid - r * C;
    const int bm = (r >= 96) ? 1 : 0;
    const int lr = r - bm * 64;
    float ssum = 0.0f;
#pragma unroll 8
    for (int s = 0; s < NSLICE; s++)
        ssum += g_partial[((size_t)s * 2 + bm) * (128 * 192) + lr * 192 + j];
    g_G[r * C + j] = ssum;
}

// ---------------------------------------------------------------------------
// Kernel 3: greedy selection — per-row minima over stable slots, with
// warp-parallel rescans of dirty rows (fixes R3's serial-tail).
// Slot order == list-position order, so key (dbits, row, partner) reproduces
// row-major first-occurrence argmin exactly.
// ---------------------------------------------------------------------------
__global__ __launch_bounds__(512) void select_kernel() {
    extern __shared__ float sD2[];                       // C*C floats
    __shared__ int  s_alive[NSLOTS];
    __shared__ int  s_chan[NSLOTS];
    __shared__ unsigned long long s_minkey[NSLOTS];
    __shared__ unsigned long long warpmin[16];
    __shared__ int s_dirty[NSLOTS];
    __shared__ int s_cnt;
    __shared__ int s_si, s_sj;

    const int tid  = threadIdx.x;
    const int wid  = tid >> 5;
    const int lane = tid & 31;

    // Build D2 in shared memory from Gram matrix.
    for (int id = tid; id < C * C; id += 512) {
        const int i = id / C;
        const int j = id - i * C;
        float d = 0.0f;
        if (i != j) {
            d = g_G[i * C + i] + g_G[j * C + j] - 2.0f * g_G[i * C + j];
            d = fmaxf(d, 0.0f);
        }
        sD2[id] = d;
    }
    if (tid < NSLOTS) {
        s_alive[tid] = (tid < C) ? 1 : 0;
        s_chan[tid]  = (tid < C) ? tid : 0;
        s_minkey[tid] = ~0ull;
    }
    __syncthreads();

    // Initial row minima: warp per row (rows 0..190; row 191 stays ~0).
    for (int row = wid; row < C - 1; row += 16) {
        const int rowbase = row * C;
        unsigned long long b = ~0ull;
        for (int sp = row + 1 + lane; sp < C; sp += 32) {
            const float d = sD2[rowbase + sp];
            const unsigned long long key =
                ((unsigned long long)__float_as_uint(d) << 32) | (unsigned)sp;
            if (key < b) b = key;
        }
#pragma unroll
        for (int o = 16; o > 0; o >>= 1) {
            unsigned long long other = __shfl_down_sync(0xffffffffu, b, o);
            if (other < b) b = other;
        }
        if (lane == 0) s_minkey[row] = b;
    }
    __syncthreads();

    for (int t = 0; t < T_STEPS; t++) {
        const int sn = C + t;

        // ---- Phase A: global argmin over row minima ----
        unsigned long long best = ~0ull;
        if (tid < sn && s_alive[tid]) {
            const unsigned long long mk = s_minkey[tid];
            if (mk != ~0ull) {
                best = ((mk >> 32) << 18) |
                       ((unsigned long long)tid << 9) | (mk & 0x1ffull);
            }
        }
#pragma unroll
        for (int o = 16; o > 0; o >>= 1) {
            unsigned long long other = __shfl_down_sync(0xffffffffu, best, o);
            if (other < best) best = other;
        }
        if (lane == 0) warpmin[wid] = best;
        __syncthreads();
        if (tid < 32) {
            best = (tid < 16) ? warpmin[tid] : ~0ull;
#pragma unroll
            for (int o = 8; o > 0; o >>= 1) {
                unsigned long long other = __shfl_down_sync(0xffffffffu, best, o);
                if (other < best) best = other;
            }
            if (tid == 0) {
                const int si = (int)((best >> 9) & 0x1ff);
                const int sj = (int)(best & 0x1ff);
                s_si = si; s_sj = sj;
                g_v1[t] = s_chan[si];
                g_v2[t] = s_chan[sj];
                s_alive[si] = 0;
                s_alive[sj] = 0;
                s_alive[sn] = 1;
                s_chan[sn]  = t;          // replicated indexing bug
                s_minkey[sn] = ~0ull;
                s_cnt = 0;
            }
        }
        __syncthreads();

        // ---- Phase B: O(1) updates + dirty detection ----
        const int si = s_si, sj = s_sj;
        if (tid < sn && s_alive[tid]) {
            const unsigned long long mk = s_minkey[tid];
            const int part = (int)(mk & 0x1ffull);
            if (mk != ~0ull && (part == si || part == sj)) {
                const int k = atomicAdd(&s_cnt, 1);
                s_dirty[k] = tid;
            } else {
                const float d = sD2[s_chan[tid] * C + t];   // vs appended slot
                const unsigned long long key =
                    ((unsigned long long)__float_as_uint(d) << 32) | (unsigned)sn;
                if (key < mk) s_minkey[tid] = key;
            }
        }
        __syncthreads();

        // ---- Phase C: warp-parallel rescan of dirty rows ----
        const int cnt = s_cnt;
        for (int k = wid; k < cnt; k += 16) {
            const int row = s_dirty[k];
            const int rowbase = s_chan[row] * C;
            unsigned long long b = ~0ull;
            for (int sp = row + 1 + lane; sp <= sn; sp += 32) {
                if (s_alive[sp]) {
                    const float d = sD2[rowbase + s_chan[sp]];
                    const unsigned long long key =
                        ((unsigned long long)__float_as_uint(d) << 32) |
                        (unsigned)sp;
                    if (key < b) b = key;
                }
            }
#pragma unroll
            for (int o = 16; o > 0; o >>= 1) {
                unsigned long long other = __shfl_down_sync(0xffffffffu, b, o);
                if (other < b) b = other;
            }
            if (lane == 0) s_minkey[row] = b;
        }
        __syncthreads();
    }
}

// ---------------------------------------------------------------------------
// Kernel 4: gather + average -> out[b][t][hw] (unchanged)
// ---------------------------------------------------------------------------
__global__ __launch_bounds__(256) void gather_kernel(const float* __restrict__ x,
                                                     float* __restrict__ out) {
    const int t = blockIdx.x;
    const int b = blockIdx.y;
    const int v1 = g_v1[t];
    const int v2 = g_v2[t];
    const float4* p1 = (const float4*)(x + ((size_t)b * C + v1) * HW);
    const float4* p2 = (const float4*)(x + ((size_t)b * C + v2) * HW);
    float4* po = (float4*)(out + ((size_t)b * T_STEPS + t) * HW);
    for (int q = threadIdx.x; q < HW / 4; q += blockDim.x) {
        const float4 a = p1[q];
        const float4 c = p2[q];
        float4 r;
        r.x = 0.5f * (a.x + c.x);
        r.y = 0.5f * (a.y + c.y);
        r.z = 0.5f * (a.z + c.z);
        r.w = 0.5f * (a.w + c.w);
        po[q] = r;
    }
}

// ---------------------------------------------------------------------------
extern "C" void kernel_launch(void* const* d_in, const int* in_sizes, int n_in,
                              void* d_out, int out_size) {
    const float* x = (const float*)d_in[0];
    float* out = (float*)d_out;

    static bool attr_set = false;
    if (!attr_set) {
        cudaFuncSetAttribute(select_kernel,
                             cudaFuncAttributeMaxDynamicSharedMemorySize,
                             SMEM_D2_BYTES);
        cudaFuncSetAttribute(gram_mma_kernel,
                             cudaFuncAttributeMaxDynamicSharedMemorySize,
                             GRAM_SMEM_BYTES);
        attr_set = true;
    }

    gram_mma_kernel<<<dim3(2, NSLICE), 256, GRAM_SMEM_BYTES>>>(x);
    reduce_kernel<<<144, 256>>>();
    select_kernel<<<1, 512, SMEM_D2_BYTES>>>();
    gather_kernel<<<dim3(T_STEPS, BATCH), 256>>>(x, out);
}